// round 15
// baseline (speedup 1.0000x reference)
#include <cuda_runtime.h>
#include <cuda_fp16.h>

#define C_IN   10
#define C_OUT  64
#define MAXM   200000
#define MAXN   2000000
#define MAXPTS 64
#define W_BEV  512
#define H_BEV  512
#define NSLOT  (4 * W_BEV * H_BEV)
#define FULLMASK 0xffffffffu

// ---- device scratch (statics; zero at load; every replay self-resets) ----
__device__ __align__(16) int   g_cnt[MAXM];                   // zeroed by k_pillar after use
__device__ __align__(16) int   g_order[MAXM * MAXPTS];        // 51.2 MB (x gather)
__device__ __align__(16) int   g_pos[MAXN];                   // 8 MB: within-pillar position
__device__ __align__(16) int   g_base[MAXM];                  // 0.8 MB: pillar base slot
__device__ int   g_total;                                     // slot counter; reset by k_bn
__device__ __align__(16) float g_s[(long long)MAXN * C_OUT];  // 512 MB (pillar-grouped!)
__device__ __align__(16) float g_pf[(long long)MAXM * C_OUT]; // 51.2 MB
__device__ __align__(16) int   g_slot[NSLOT];                 // pillar+1; reset by k_scatter
__device__ __align__(16) float g_xsum[C_IN];                  // zeroed by k_bn after use
__device__ __align__(16) float g_xcov[55];                    // zeroed by k_bn after use
__device__ __align__(16) float g_a[C_OUT];
__device__ __align__(16) float g_b[C_OUT];

// ---- packed f32x2 helpers ----
typedef unsigned long long u64;
typedef unsigned int u32;
__device__ __forceinline__ u64 pk2(float lo, float hi) {
    u64 r; asm("mov.b64 %0, {%1,%2};" : "=l"(r) : "f"(lo), "f"(hi)); return r;
}
__device__ __forceinline__ void upk2(u64 v, float& lo, float& hi) {
    asm("mov.b64 {%0,%1}, %2;" : "=f"(lo), "=f"(hi) : "l"(v));
}
__device__ __forceinline__ u64 fma2(u64 a, u64 b, u64 c) {
    u64 d; asm("fma.rn.f32x2 %0, %1, %2, %3;" : "=l"(d) : "l"(a), "l"(b), "l"(c)); return d;
}

// ---- fp16 m16n8k16 mma, f32 accumulate ----
__device__ __forceinline__ void mma16(float d[4], const u32 a[4], const u32 b[2]) {
    asm volatile("mma.sync.aligned.m16n8k16.row.col.f32.f16.f16.f32 "
        "{%0,%1,%2,%3},{%4,%5,%6,%7},{%8,%9},{%0,%1,%2,%3};"
        : "+f"(d[0]), "+f"(d[1]), "+f"(d[2]), "+f"(d[3])
        : "r"(a[0]), "r"(a[1]), "r"(a[2]), "r"(a[3]), "r"(b[0]), "r"(b[1]));
}

// fp32 pair -> fp16 hi + fp16 lo residual (packed u32 each)
__device__ __forceinline__ void hilo2(float v0, float v1, u32& hi, u32& lo) {
    __half2 H = __float22half2_rn(make_float2(v0, v1));
    float2 Hf = __half22float2(H);
    __half2 L = __float22half2_rn(make_float2(v0 - Hf.x, v1 - Hf.y));
    hi = *(u32*)&H;
    lo = *(u32*)&L;
}

// ---------------------------------------------------------------------------
// K1: x first/second moments (block-level reduction, 65 atomics/block)
// ---------------------------------------------------------------------------
__global__ void __launch_bounds__(256) k_mom(const float* __restrict__ gf, int N)
{
    __shared__ float red[8][65];
    float sx[C_IN];
    float sxx[55];
#pragma unroll
    for (int i = 0; i < C_IN; i++) sx[i] = 0.f;
#pragma unroll
    for (int i = 0; i < 55; i++) sxx[i] = 0.f;

    const int stride = gridDim.x * blockDim.x;
    for (int p = blockIdx.x * blockDim.x + threadIdx.x; p < N; p += stride) {
        float x[C_IN];
        const float2* xr = (const float2*)(gf + (long long)p * C_IN);
#pragma unroll
        for (int k = 0; k < C_IN / 2; k++) {
            float2 v = __ldg(xr + k);
            x[2 * k] = v.x; x[2 * k + 1] = v.y;
        }
        int t = 0;
#pragma unroll
        for (int i = 0; i < C_IN; i++) {
            sx[i] += x[i];
#pragma unroll
            for (int j = 0; j <= i; j++) { sxx[t] = fmaf(x[i], x[j], sxx[t]); t++; }
        }
    }

    const int lane = threadIdx.x & 31;
    const int wid  = threadIdx.x >> 5;
#pragma unroll
    for (int i = 0; i < C_IN; i++) {
        float v = sx[i];
#pragma unroll
        for (int o = 16; o > 0; o >>= 1) v += __shfl_down_sync(FULLMASK, v, o);
        if (lane == 0) red[wid][i] = v;
    }
#pragma unroll
    for (int i = 0; i < 55; i++) {
        float v = sxx[i];
#pragma unroll
        for (int o = 16; o > 0; o >>= 1) v += __shfl_down_sync(FULLMASK, v, o);
        if (lane == 0) red[wid][C_IN + i] = v;
    }
    __syncthreads();
    if (threadIdx.x < 65) {
        float v = 0.f;
#pragma unroll
        for (int w = 0; w < 8; w++) v += red[w][threadIdx.x];
        if (threadIdx.x < C_IN) atomicAdd(&g_xsum[threadIdx.x], v);
        else                    atomicAdd(&g_xcov[threadIdx.x - C_IN], v);
    }
}

// ---------------------------------------------------------------------------
// K2: BN affine params from x moments; resets moment accumulators + g_total
// ---------------------------------------------------------------------------
__global__ void k_bn(const float* __restrict__ W0, const float* __restrict__ gamma,
                     const float* __restrict__ beta, float invN)
{
    int c = threadIdx.x;
    if (c < C_OUT) {
        float w[C_IN];
#pragma unroll
        for (int i = 0; i < C_IN; i++) w[i] = W0[i * C_OUT + c];
        float mu = 0.f;
#pragma unroll
        for (int i = 0; i < C_IN; i++) mu = fmaf(g_xsum[i] * invN, w[i], mu);
        float ex2 = 0.f;
        int t = 0;
#pragma unroll
        for (int i = 0; i < C_IN; i++) {
#pragma unroll
            for (int j = 0; j <= i; j++) {
                float s = g_xcov[t++] * invN;
                float coef = (i == j) ? 1.f : 2.f;
                ex2 = fmaf(coef * s, w[i] * w[j], ex2);
            }
        }
        float var = fmaf(-mu, mu, ex2);
        float rstd = rsqrtf(var + 1e-3f);
        float a = rstd * gamma[c];
        g_a[c] = a;
        g_b[c] = fmaf(-mu, a, beta[c]);
    }
    __syncthreads();
    if (c < C_IN) g_xsum[c] = 0.f;
    if (c < 55)  g_xcov[c] = 0.f;
    if (c == 63) g_total = 0;
}

// ---------------------------------------------------------------------------
// K3: bucket point ids by pillar; record within-pillar position per point
// ---------------------------------------------------------------------------
__global__ void __launch_bounds__(256) k_count(const int* __restrict__ psi, int N)
{
    const int stride = gridDim.x * blockDim.x;
    for (int p = blockIdx.x * blockDim.x + threadIdx.x; p < N; p += stride) {
        int idx = __ldg(psi + p);
        int pos = atomicAdd(&g_cnt[idx], 1);
        if (pos < MAXPTS) {
            g_order[idx * MAXPTS + pos] = p;
            g_pos[p] = pos;
        } else {
            g_pos[p] = -1;
        }
    }
}

// ---------------------------------------------------------------------------
// K4: exclusive prefix over clamped counts -> g_base (block scan + 1 atomic)
// ---------------------------------------------------------------------------
__global__ void __launch_bounds__(256) k_base(int M)
{
    __shared__ int wsum[8];
    __shared__ int bstart;
    const int i = blockIdx.x * 256 + threadIdx.x;
    const int lane = threadIdx.x & 31, wid = threadIdx.x >> 5;
    const int c = (i < M) ? min(g_cnt[i], MAXPTS) : 0;
    int v = c;
#pragma unroll
    for (int o = 1; o < 32; o <<= 1) {
        int n = __shfl_up_sync(FULLMASK, v, o);
        if (lane >= o) v += n;
    }
    if (lane == 31) wsum[wid] = v;
    __syncthreads();
    if (threadIdx.x == 0) {
        int s = 0;
#pragma unroll
        for (int w = 0; w < 8; w++) { int t = wsum[w]; wsum[w] = s; s += t; }
        bstart = atomicAdd(&g_total, s);
    }
    __syncthreads();
    if (i < M) g_base[i] = bstart + wsum[wid] + v - c;
}

// ---------------------------------------------------------------------------
// K5: dual tensor-core GEMM (register-fused); stores s PILLAR-GROUPED:
//     slot = g_base[psi[p]] + g_pos[p]  (scattered-base writes, streaming reads)
// ---------------------------------------------------------------------------
#define TP  128
#define SK  72    // Ws row stride in halves
#define W0S 24    // W0 row stride in halves

__global__ void __launch_bounds__(128) k_sgemm(
    const float* __restrict__ gf, const int* __restrict__ psi,
    const float* __restrict__ W0, const float* __restrict__ Ws,
    const float* __restrict__ bs, int N)
{
    __shared__ __half sBhi[C_OUT * SK];
    __shared__ __half sBlo[C_OUT * SK];
    __shared__ __half sW0hi[C_OUT * W0S];
    __shared__ __half sW0lo[C_OUT * W0S];

    const int tid = threadIdx.x, lane = tid & 31, w = tid >> 5;
    const int p0 = blockIdx.x * TP;
    const int g = lane >> 2, t = lane & 3;

    for (int i = tid; i < C_OUT * C_OUT; i += 128) {
        int k = i >> 6, n = i & 63;
        float v = __ldg(Ws + i);
        __half hi = __float2half_rn(v);
        __half lo = __float2half_rn(v - __half2float(hi));
        sBhi[n * SK + k] = hi;
        sBlo[n * SK + k] = lo;
    }
    for (int i = tid; i < C_OUT * 16; i += 128) {
        int k = i & 15, n = i >> 4;
        float v = (k < C_IN) ? __ldg(W0 + k * C_OUT + n) : 0.f;
        __half hi = __float2half_rn(v);
        __half lo = __float2half_rn(v - __half2float(hi));
        sW0hi[n * W0S + k] = hi;
        sW0lo[n * W0S + k] = lo;
    }
    __syncthreads();

#pragma unroll 1
    for (int mi = 0; mi < 2; mi++) {
        const int rb = w * 32 + mi * 16;
        const long long r0 = (long long)p0 + rb + g;
        const long long r1 = r0 + 8;
        const bool v0 = r0 < N, v1 = r1 < N;

        float2 xa = make_float2(0.f, 0.f), xb = xa, xc = xa, xd = xa;
        if (v0) xa = __ldg((const float2*)(gf + r0 * C_IN) + t);
        if (v1) xb = __ldg((const float2*)(gf + r1 * C_IN) + t);
        if (t == 0) {
            if (v0) xc = __ldg((const float2*)(gf + r0 * C_IN) + 4);
            if (v1) xd = __ldg((const float2*)(gf + r1 * C_IN) + 4);
        }
        u32 axhi[4], axlo[4];
        hilo2(xa.x, xa.y, axhi[0], axlo[0]);
        hilo2(xb.x, xb.y, axhi[1], axlo[1]);
        hilo2(xc.x, xc.y, axhi[2], axlo[2]);
        hilo2(xd.x, xd.y, axhi[3], axlo[3]);

        float acc1[8][4];
#pragma unroll
        for (int ni = 0; ni < 8; ni++)
#pragma unroll
            for (int q = 0; q < 4; q++) acc1[ni][q] = 0.f;

#pragma unroll
        for (int ni = 0; ni < 8; ni++) {
            const int n = ni * 8 + g;
            u32 bh[2], bl[2];
            bh[0] = *(const u32*)&sW0hi[n * W0S + 2 * t];
            bh[1] = *(const u32*)&sW0hi[n * W0S + 2 * t + 8];
            bl[0] = *(const u32*)&sW0lo[n * W0S + 2 * t];
            bl[1] = *(const u32*)&sW0lo[n * W0S + 2 * t + 8];
            mma16(acc1[ni], axhi, bl);
            mma16(acc1[ni], axlo, bh);
            mma16(acc1[ni], axhi, bh);
        }

        u32 a2hi[4][4], a2lo[4][4];
#pragma unroll
        for (int ni = 0; ni < 8; ni++) {
            float2 ga = __ldg((const float2*)(g_a + ni * 8) + t);
            float2 gb = __ldg((const float2*)(g_b + ni * 8) + t);
            float h0 = fmaxf(fmaf(acc1[ni][0], ga.x, gb.x), 0.f);
            float h1 = fmaxf(fmaf(acc1[ni][1], ga.y, gb.y), 0.f);
            float h2 = fmaxf(fmaf(acc1[ni][2], ga.x, gb.x), 0.f);
            float h3 = fmaxf(fmaf(acc1[ni][3], ga.y, gb.y), 0.f);
            const int ks = ni >> 1, o = (ni & 1) ? 2 : 0;
            hilo2(h0, h1, a2hi[ks][o + 0], a2lo[ks][o + 0]);
            hilo2(h2, h3, a2hi[ks][o + 1], a2lo[ks][o + 1]);
        }

        float acc2[8][4];
#pragma unroll
        for (int ni = 0; ni < 8; ni++)
#pragma unroll
            for (int q = 0; q < 4; q++) acc2[ni][q] = 0.f;

#pragma unroll
        for (int ks = 0; ks < 4; ks++) {
#pragma unroll
            for (int ni = 0; ni < 8; ni++) {
                const int n = ni * 8 + g;
                u32 bh[2], bl[2];
                bh[0] = *(const u32*)&sBhi[n * SK + 16 * ks + 2 * t];
                bh[1] = *(const u32*)&sBhi[n * SK + 16 * ks + 2 * t + 8];
                bl[0] = *(const u32*)&sBlo[n * SK + 16 * ks + 2 * t];
                bl[1] = *(const u32*)&sBlo[n * SK + 16 * ks + 2 * t + 8];
                mma16(acc2[ni], a2hi[ks], bl);
                mma16(acc2[ni], a2lo[ks], bh);
                mma16(acc2[ni], a2hi[ks], bh);
            }
        }

        // ---- store s (pre-relu) to pillar-grouped slots ----
        long long sl0 = -1, sl1 = -1;
        if (v0) {
            int pp = __ldg(g_pos + r0);
            if (pp >= 0) sl0 = (long long)__ldg(g_base + __ldg(psi + r0)) + pp;
        }
        if (v1) {
            int pp = __ldg(g_pos + r1);
            if (pp >= 0) sl1 = (long long)__ldg(g_base + __ldg(psi + r1)) + pp;
        }
#pragma unroll
        for (int ni = 0; ni < 8; ni++) {
            float2 bv = __ldg((const float2*)(bs + ni * 8) + t);
            const int c = ni * 8 + 2 * t;
            if (sl0 >= 0)
                *(float2*)(g_s + sl0 * C_OUT + c) =
                    make_float2(acc2[ni][0] + bv.x, acc2[ni][1] + bv.y);
            if (sl1 >= 0)
                *(float2*)(g_s + sl1 * C_OUT + c) =
                    make_float2(acc2[ni][2] + bv.x, acc2[ni][3] + bv.y);
        }
    }
}

// ---------------------------------------------------------------------------
// K6: warp-per-pillar gather; s rows now CONTIGUOUS (streaming), x gathered.
// ---------------------------------------------------------------------------
__global__ void __launch_bounds__(128) k_pillar(
    const float* __restrict__ gf, const float* __restrict__ W0, int M)
{
    const int lane = threadIdx.x & 31;
    const int pillar = blockIdx.x * 4 + (threadIdx.x >> 5);
    if (pillar >= M) return;
    const int c0 = 2 * lane;

    u64 w0v[C_IN];
#pragma unroll
    for (int k = 0; k < C_IN; k++) {
        float2 ww = *(const float2*)(W0 + k * C_OUT + c0);
        w0v[k] = pk2(ww.x, ww.y);
    }
    const float2 a2 = *(const float2*)(g_a + c0);
    const float2 b2 = *(const float2*)(g_b + c0);
    const u64 av = pk2(a2.x, a2.y);
    const u64 bv = pk2(b2.x, b2.y);

    const int cnt = min(g_cnt[pillar], MAXPTS);
    if (lane == 0) g_cnt[pillar] = 0;           // replay reset
    const long long sbase = __ldg(g_base + pillar);
    const float* __restrict__ srow = g_s + sbase * C_OUT;
    const int* __restrict__ ord = g_order + pillar * MAXPTS;
    const int myp0 = __ldg(ord + lane);
    const int myp1 = __ldg(ord + 32 + lane);

    float denx = 0.f, deny = 0.f;
    float numx = 0.f, numy = 0.f;
    float mxhx = 0.f, mxhy = 0.f;

    float2 sv0, sv1;
    float2 xv0[C_IN / 2], xv1[C_IN / 2];

#define GETP(j)  __shfl_sync(FULLMASK, ((j) < 32 ? myp0 : myp1), (j) & 31)
#define PREF(SV, XV, j) { \
        int _p = GETP(j); \
        SV = __ldg((const float2*)(srow + (long long)(j) * C_OUT) + lane); \
        const float2* _xr = (const float2*)(gf + (long long)_p * C_IN); \
        _Pragma("unroll") \
        for (int _k = 0; _k < C_IN / 2; _k++) XV[_k] = __ldg(_xr + _k); }

#define BODY(SV, XV) { \
        u64 hv = 0; \
        _Pragma("unroll") \
        for (int _k = 0; _k < C_IN / 2; _k++) { \
            hv = fma2(pk2(XV[_k].x, XV[_k].x), w0v[2 * _k],     hv); \
            hv = fma2(pk2(XV[_k].y, XV[_k].y), w0v[2 * _k + 1], hv); \
        } \
        hv = fma2(hv, av, bv); \
        float hx, hy; upk2(hv, hx, hy); \
        hx = fmaxf(hx, 0.f); hy = fmaxf(hy, 0.f); \
        float ex = __expf(fmaxf(SV.x, 0.f)); \
        float ey = __expf(fmaxf(SV.y, 0.f)); \
        denx += ex; numx = fmaf(ex, hx, numx); mxhx = fmaxf(mxhx, hx); \
        deny += ey; numy = fmaf(ey, hy, numy); mxhy = fmaxf(mxhy, hy); }

    if (cnt > 0) PREF(sv0, xv0, 0);
    if (cnt > 1) PREF(sv1, xv1, 1);

    int j = 0;
    while (j < cnt) {
        BODY(sv0, xv0);
        if (j + 2 < cnt) PREF(sv0, xv0, j + 2);
        j++;
        if (j >= cnt) break;
        BODY(sv1, xv1);
        if (j + 2 < cnt) PREF(sv1, xv1, j + 2);
        j++;
    }

    float pfx = 0.5f * (numx / denx + mxhx);
    float pfy = 0.5f * (numy / deny + mxhy);
    if (cnt == 0) { pfx = 0.f; pfy = 0.f; }

    *(float2*)&g_pf[(long long)pillar * C_OUT + c0] = make_float2(pfx, pfy);
}

// ---------------------------------------------------------------------------
// K7: inverse map slot -> pillar+1 (0 = empty; scatter resets to 0)
// ---------------------------------------------------------------------------
__global__ void k_slot(const int* __restrict__ pind, int M) {
    int p = blockIdx.x * blockDim.x + threadIdx.x;
    if (p < M) {
        int b = __ldg(pind + p * 3 + 0);
        int x = __ldg(pind + p * 3 + 1);
        int y = __ldg(pind + p * 3 + 2);
        g_slot[b * (W_BEV * H_BEV) + x * H_BEV + y] = p + 1;
    }
}

// ---------------------------------------------------------------------------
// K8: canvas fill, single-touch; resets its slot row to 0 after staging.
// ---------------------------------------------------------------------------
__global__ void __launch_bounds__(256) k_scatter(float* __restrict__ out)
{
    __shared__ int slots[H_BEV];
    const int bx = blockIdx.x;
    const int b = bx >> 9, x = bx & 511;
    const int tid = threadIdx.x;

    ((int2*)slots)[tid] = *(const int2*)&g_slot[bx * H_BEV + 2 * tid];
    __syncthreads();
    *(int2*)&g_slot[bx * H_BEV + 2 * tid] = make_int2(0, 0);   // replay reset

    const int y0 = 2 * tid;
    const int s0 = slots[y0] - 1, s1 = slots[y0 + 1] - 1;
    const float* p0 = g_pf + (long long)s0 * C_OUT;
    const float* p1 = g_pf + (long long)s1 * C_OUT;
    const long long obase = ((long long)b * C_OUT * W_BEV + x) * H_BEV + y0;
    const float4 z = make_float4(0.f, 0.f, 0.f, 0.f);

#pragma unroll
    for (int cg = 0; cg < 8; cg++) {
        float4 a0 = z, a1 = z, c0v = z, c1v = z;
        if (s0 >= 0) {
            a0  = __ldg((const float4*)(p0 + cg * 8));
            c0v = __ldg((const float4*)(p0 + cg * 8 + 4));
        }
        if (s1 >= 0) {
            a1  = __ldg((const float4*)(p1 + cg * 8));
            c1v = __ldg((const float4*)(p1 + cg * 8 + 4));
        }
        float va[8] = {a0.x, a0.y, a0.z, a0.w, c0v.x, c0v.y, c0v.z, c0v.w};
        float vb[8] = {a1.x, a1.y, a1.z, a1.w, c1v.x, c1v.y, c1v.z, c1v.w};
#pragma unroll
        for (int jj = 0; jj < 8; jj++) {
            int c = cg * 8 + jj;
            *(float2*)&out[obase + (long long)c * (W_BEV * H_BEV)] = make_float2(va[jj], vb[jj]);
        }
    }
}

// ---------------------------------------------------------------------------
extern "C" void kernel_launch(void* const* d_in, const int* in_sizes, int n_in,
                              void* d_out, int out_size)
{
    const float* gf    = (const float*)d_in[0];
    const int*   psi   = (const int*)  d_in[1];
    const int*   pind  = (const int*)  d_in[2];
    const float* W0    = (const float*)d_in[3];
    const float* gamma = (const float*)d_in[4];
    const float* beta  = (const float*)d_in[5];
    const float* Ws    = (const float*)d_in[6];
    const float* bs    = (const float*)d_in[7];
    float* out = (float*)d_out;

    const int N = in_sizes[0] / C_IN;
    const int M = in_sizes[2] / 3;

    k_mom    <<<1480, 256>>>(gf, N);                        // 1
    k_bn     <<<1, 64>>>(W0, gamma, beta, 1.0f / (float)N); // 2
    k_count  <<<2048, 256>>>(psi, N);                       // 3
    k_base   <<<(M + 255) / 256, 256>>>(M);                 // 4
    k_sgemm  <<<(N + TP - 1) / TP, 128>>>(gf, psi, W0, Ws, bs, N); // 5
    k_pillar <<<(M + 3) / 4, 128>>>(gf, W0, M);             // 6
    k_slot   <<<(M + 255) / 256, 256>>>(pind, M);           // 7
    k_scatter<<<4 * W_BEV, 256>>>(out);                     // 8
}